// round 12
// baseline (speedup 1.0000x reference)
#include <cuda_runtime.h>
#include <cstddef>

// GRU (B rows, T=1024, D=6, H=48) + fused FC.
// Block = 96 threads (3 warps), R=4 batch rows, grid 512 = single wave.
// Warp w owns outputs i = w*16 + (lane&15); k-half s = lane>>4.
// P1: each thread computes k-half dots of all 3 gates for output i, ALL 4 rows
//     (weight-register reuse). Exchange via shfl_xor(16): 4 quantities/row.
// Combine split BY ROW: s=0 lanes finish rows 0-1, s=1 lanes rows 2-3
//     (non-redundant MUFU, divergence-free). h,x pingpong -> ONE barrier/step.
// fc fused: thread = (rowA=tid/48 & rowA+2, d=(tid%48)>>3, c=(tid%48)&7).

#define T_SEQ 1024
#define D_IN  6
#define HDIM  48
#define KH    24
#define R     4
#define NTHR  96

__device__ __forceinline__ float2 ffma2(float2 a, float2 b, float2 c) {
    union U { float2 f; unsigned long long u; };
    U ua, ub, uc, ud;
    ua.f = a; ub.f = b; uc.f = c;
    asm("fma.rn.f32x2 %0, %1, %2, %3;" : "=l"(ud.u) : "l"(ua.u), "l"(ub.u), "l"(uc.u));
    return ud.f;
}

__device__ __forceinline__ float fast_sigmoid(float x) {
    float e = __expf(-x);
    return __fdividef(1.0f, 1.0f + e);
}
__device__ __forceinline__ float fast_tanh(float x) {
    float a = fabsf(x);
    float e = __expf(2.0f * a);
    float r = 1.0f - __fdividef(2.0f, e + 1.0f);
    return copysignf(r, x);
}

__global__ void __launch_bounds__(NTHR, 4)
gru_fused_kernel(const float* __restrict__ x,
                 const float* __restrict__ W_ih,   // [144, 6]
                 const float* __restrict__ W_hh,   // [144, 48]
                 const float* __restrict__ b_ih,   // [144]
                 const float* __restrict__ b_hh,   // [144]
                 const float* __restrict__ fc_w,   // [6, 48]
                 const float* __restrict__ fc_b,   // [6]
                 float* __restrict__ y,            // [B, T, 6]
                 int B)
{
    __shared__ __align__(16) float h_s[2][R][HDIM];
    __shared__ __align__(16) float x_s[2][R][8];

    const int tid  = threadIdx.x;
    const int w    = tid >> 5;
    const int lane = tid & 31;
    const int sh   = lane >> 4;          // k-half / d-half / combine row-pair
    const int io   = lane & 15;
    const int i    = w * 16 + io;        // owned output index 0..47
    const int b0   = blockIdx.x * R;

    // ---- recurrent weights: W_hh[g*48+i][sh*24 .. sh*24+23] -> 12 f32x2 / gate ----
    float2 whr[12], whz[12], whn[12];
    {
        const float4* pr = reinterpret_cast<const float4*>(W_hh + ((size_t)(0 * HDIM + i) * HDIM + sh * KH));
        const float4* pz = reinterpret_cast<const float4*>(W_hh + ((size_t)(1 * HDIM + i) * HDIM + sh * KH));
        const float4* pn = reinterpret_cast<const float4*>(W_hh + ((size_t)(2 * HDIM + i) * HDIM + sh * KH));
        #pragma unroll
        for (int q = 0; q < 6; q++) {
            float4 v;
            v = pr[q]; whr[2*q] = make_float2(v.x, v.y); whr[2*q+1] = make_float2(v.z, v.w);
            v = pz[q]; whz[2*q] = make_float2(v.x, v.y); whz[2*q+1] = make_float2(v.z, v.w);
            v = pn[q]; whn[2*q] = make_float2(v.x, v.y); whn[2*q+1] = make_float2(v.z, v.w);
        }
    }
    // ---- gi weights: d-half (3 inputs), partial folded into the shuffles ----
    float wir[3], wiz[3], win[3];
    #pragma unroll
    for (int j = 0; j < 3; j++) {
        wir[j] = W_ih[(size_t)(0 * HDIM + i) * D_IN + sh * 3 + j];
        wiz[j] = W_ih[(size_t)(1 * HDIM + i) * D_IN + sh * 3 + j];
        win[j] = W_ih[(size_t)(2 * HDIM + i) * D_IN + sh * 3 + j];
    }
    const float brr = b_ih[i]            + b_hh[i];
    const float bzz = b_ih[HDIM + i]     + b_hh[HDIM + i];
    const float bin = b_ih[2 * HDIM + i];
    const float bhn = b_hh[2 * HDIM + i];

    // ---- fc role ----
    const int i2   = tid % HDIM;
    const int rcA  = tid / HDIM;         // 0 or 1 (also handles rcA+2)
    const int d_fc = i2 >> 3;
    const int c_fc = i2 & 7;             // == lane&7 for all tid (48%8==0)
    float2 fw[3];
    {
        const float2* p = reinterpret_cast<const float2*>(fc_w + (size_t)d_fc * HDIM + c_fc * 6);
        fw[0] = p[0]; fw[1] = p[1]; fw[2] = p[2];
    }
    const float fb = fc_b[d_fc];
    float* yA = y + (size_t)(b0 + rcA)     * T_SEQ * D_IN;
    float* yB = y + (size_t)(b0 + rcA + 2) * T_SEQ * D_IN;
    const bool vA = (b0 + rcA)     < B;
    const bool vB = (b0 + rcA + 2) < B;

    // ---- init ----
    float hc[2] = {0.0f, 0.0f};          // states for rows 2*sh, 2*sh+1 (output i)
    #pragma unroll
    for (int r = 0; r < R; r++) { if (sh == 0) h_s[0][r][i] = 0.0f; }
    if (tid < R * D_IN) {
        int rr = tid / D_IN, dd = tid - rr * D_IN;
        x_s[0][rr][dd] = ((b0 + rr) < B) ? x[((size_t)(b0 + rr) * T_SEQ) * D_IN + dd] : 0.0f;
    }
    __syncthreads();

    const float2 z2 = make_float2(0.0f, 0.0f);
    int p = 0;

    for (int t = 0; t < T_SEQ; t++) {
        // ---- prefetch x[t+1] ----
        float xn = 0.0f;
        if (tid < R * D_IN && (t + 1) < T_SEQ) {
            int rr = tid / D_IN, dd = tid - rr * D_IN;
            if ((b0 + rr) < B) xn = x[((size_t)(b0 + rr) * T_SEQ + (t + 1)) * D_IN + dd];
        }

        // ---- P1: half-dots + shfl exchange, all 4 rows ----
        float fr[2], fz[2], fhn[2], fgn[2];
        #pragma unroll
        for (int r = 0; r < R; r++) {
            float2 a_r = z2, a_z = z2, a_n = z2;
            const float4* h4 = reinterpret_cast<const float4*>(&h_s[p][r][sh * KH]);
            #pragma unroll
            for (int q = 0; q < 6; q++) {
                float4 hv = h4[q];
                float2 h01 = make_float2(hv.x, hv.y);
                float2 h23 = make_float2(hv.z, hv.w);
                a_r = ffma2(whr[2*q], h01, a_r); a_r = ffma2(whr[2*q+1], h23, a_r);
                a_z = ffma2(whz[2*q], h01, a_z); a_z = ffma2(whz[2*q+1], h23, a_z);
                a_n = ffma2(whn[2*q], h01, a_n); a_n = ffma2(whn[2*q+1], h23, a_n);
            }
            float g_r = 0.f, g_z = 0.f, g_n = 0.f;
            #pragma unroll
            for (int j = 0; j < 3; j++) {
                float xv = x_s[p][r][sh * 3 + j];
                g_r = fmaf(wir[j], xv, g_r);
                g_z = fmaf(wiz[j], xv, g_z);
                g_n = fmaf(win[j], xv, g_n);
            }
            float sr  = a_r.x + a_r.y + g_r;     // gh_r half + gi_r half
            float sz  = a_z.x + a_z.y + g_z;
            float shn = a_n.x + a_n.y;            // gh_n half (separate)
            float sgn = g_n;                      // gi_n half (separate)
            sr  += __shfl_xor_sync(0xffffffffu, sr,  16);
            sz  += __shfl_xor_sync(0xffffffffu, sz,  16);
            shn += __shfl_xor_sync(0xffffffffu, shn, 16);
            sgn += __shfl_xor_sync(0xffffffffu, sgn, 16);
            if (sh == (r >> 1)) {                 // stash: my row-pair only
                fr[r & 1] = sr; fz[r & 1] = sz; fhn[r & 1] = shn; fgn[r & 1] = sgn;
            }
        }

        // ---- fused fc on h_{t-1} (h_s[p] untouched this step) ----
        if (t > 0) {
            const float2* hcA = reinterpret_cast<const float2*>(&h_s[p][rcA][c_fc * 6]);
            const float2* hcB = reinterpret_cast<const float2*>(&h_s[p][rcA + 2][c_fc * 6]);
            float2 aA = ffma2(fw[0], hcA[0], z2);
            float2 aB = ffma2(fw[0], hcB[0], z2);
            aA = ffma2(fw[1], hcA[1], aA);
            aB = ffma2(fw[1], hcB[1], aB);
            aA = ffma2(fw[2], hcA[2], aA);
            aB = ffma2(fw[2], hcB[2], aB);
            float pA = aA.x + aA.y;
            float pB = aB.x + aB.y;
            pA += __shfl_down_sync(0xffffffffu, pA, 4, 8);
            pB += __shfl_down_sync(0xffffffffu, pB, 4, 8);
            pA += __shfl_down_sync(0xffffffffu, pA, 2, 8);
            pB += __shfl_down_sync(0xffffffffu, pB, 2, 8);
            pA += __shfl_down_sync(0xffffffffu, pA, 1, 8);
            pB += __shfl_down_sync(0xffffffffu, pB, 1, 8);
            if (c_fc == 0) {
                if (vA) yA[(size_t)(t - 1) * D_IN + d_fc] = pA + fb;
                if (vB) yB[(size_t)(t - 1) * D_IN + d_fc] = pB + fb;
            }
        }

        // ---- combine: lanes sh finish rows 2*sh, 2*sh+1 (non-redundant MUFU) ----
        #pragma unroll
        for (int c = 0; c < 2; c++) {
            float rg = fast_sigmoid(fr[c] + brr);
            float zg = fast_sigmoid(fz[c] + bzz);
            float ng = fast_tanh((fgn[c] + bin) + rg * (fhn[c] + bhn));
            hc[c] = ng + zg * (hc[c] - ng);
            h_s[p ^ 1][2 * sh + c][i] = hc[c];
        }
        if (tid < R * D_IN) {
            int rr = tid / D_IN, dd = tid - rr * D_IN;
            x_s[p ^ 1][rr][dd] = xn;
        }
        __syncthreads();
        p ^= 1;
    }

    // ---- fc for final h_{T-1} ----
    {
        const float2* hcA = reinterpret_cast<const float2*>(&h_s[p][rcA][c_fc * 6]);
        const float2* hcB = reinterpret_cast<const float2*>(&h_s[p][rcA + 2][c_fc * 6]);
        float2 aA = ffma2(fw[0], hcA[0], z2);
        float2 aB = ffma2(fw[0], hcB[0], z2);
        aA = ffma2(fw[1], hcA[1], aA);
        aB = ffma2(fw[1], hcB[1], aB);
        aA = ffma2(fw[2], hcA[2], aA);
        aB = ffma2(fw[2], hcB[2], aB);
        float pA = aA.x + aA.y;
        float pB = aB.x + aB.y;
        pA += __shfl_down_sync(0xffffffffu, pA, 4, 8);
        pB += __shfl_down_sync(0xffffffffu, pB, 4, 8);
        pA += __shfl_down_sync(0xffffffffu, pA, 2, 8);
        pB += __shfl_down_sync(0xffffffffu, pB, 2, 8);
        pA += __shfl_down_sync(0xffffffffu, pA, 1, 8);
        pB += __shfl_down_sync(0xffffffffu, pB, 1, 8);
        if (c_fc == 0) {
            if (vA) yA[(size_t)(T_SEQ - 1) * D_IN + d_fc] = pA + fb;
            if (vB) yB[(size_t)(T_SEQ - 1) * D_IN + d_fc] = pB + fb;
        }
    }
}

extern "C" void kernel_launch(void* const* d_in, const int* in_sizes, int n_in,
                              void* d_out, int out_size)
{
    const float* x    = (const float*)d_in[0];
    const float* W_ih = (const float*)d_in[1];
    const float* W_hh = (const float*)d_in[2];
    const float* b_ih = (const float*)d_in[3];
    const float* b_hh = (const float*)d_in[4];
    const float* fc_w = (const float*)d_in[5];
    const float* fc_b = (const float*)d_in[6];
    float* y = (float*)d_out;

    int B = in_sizes[0] / (T_SEQ * D_IN);
    int blocks = (B + R - 1) / R;
    gru_fused_kernel<<<blocks, NTHR>>>(x, W_ih, W_hh, b_ih, b_hh, fc_w, fc_b, y, B);
}

// round 13
// speedup vs baseline: 1.0022x; 1.0022x over previous
#include <cuda_runtime.h>
#include <cstddef>

// GRU (B rows, T=1024, D=6, H=48) + fused FC.
// Block = 96 threads (3 warps), R=4 batch rows, grid 512 = single wave.
// Warp w owns outputs i = w*16 + (lane&15); k-half s = lane>>4.
// P1: each thread computes k-half dots of all 3 gates for output i, ALL 4 rows
//     (weight-register reuse). Exchange via shfl_xor(16): 4 quantities/row.
// Combine split BY ROW: s=0 lanes finish rows 0-1, s=1 lanes rows 2-3
//     (non-redundant MUFU, divergence-free). h,x pingpong -> ONE barrier/step.
// fc fused: thread = (rowA=tid/48 & rowA+2, d=(tid%48)>>3, c=(tid%48)&7).

#define T_SEQ 1024
#define D_IN  6
#define HDIM  48
#define KH    24
#define R     4
#define NTHR  96

__device__ __forceinline__ float2 ffma2(float2 a, float2 b, float2 c) {
    union U { float2 f; unsigned long long u; };
    U ua, ub, uc, ud;
    ua.f = a; ub.f = b; uc.f = c;
    asm("fma.rn.f32x2 %0, %1, %2, %3;" : "=l"(ud.u) : "l"(ua.u), "l"(ub.u), "l"(uc.u));
    return ud.f;
}

__device__ __forceinline__ float fast_sigmoid(float x) {
    float e = __expf(-x);
    return __fdividef(1.0f, 1.0f + e);
}
__device__ __forceinline__ float fast_tanh(float x) {
    float a = fabsf(x);
    float e = __expf(2.0f * a);
    float r = 1.0f - __fdividef(2.0f, e + 1.0f);
    return copysignf(r, x);
}

__global__ void __launch_bounds__(NTHR, 4)
gru_fused_kernel(const float* __restrict__ x,
                 const float* __restrict__ W_ih,   // [144, 6]
                 const float* __restrict__ W_hh,   // [144, 48]
                 const float* __restrict__ b_ih,   // [144]
                 const float* __restrict__ b_hh,   // [144]
                 const float* __restrict__ fc_w,   // [6, 48]
                 const float* __restrict__ fc_b,   // [6]
                 float* __restrict__ y,            // [B, T, 6]
                 int B)
{
    __shared__ __align__(16) float h_s[2][R][HDIM];
    __shared__ __align__(16) float x_s[2][R][8];

    const int tid  = threadIdx.x;
    const int w    = tid >> 5;
    const int lane = tid & 31;
    const int sh   = lane >> 4;          // k-half / d-half / combine row-pair
    const int io   = lane & 15;
    const int i    = w * 16 + io;        // owned output index 0..47
    const int b0   = blockIdx.x * R;

    // ---- recurrent weights: W_hh[g*48+i][sh*24 .. sh*24+23] -> 12 f32x2 / gate ----
    float2 whr[12], whz[12], whn[12];
    {
        const float4* pr = reinterpret_cast<const float4*>(W_hh + ((size_t)(0 * HDIM + i) * HDIM + sh * KH));
        const float4* pz = reinterpret_cast<const float4*>(W_hh + ((size_t)(1 * HDIM + i) * HDIM + sh * KH));
        const float4* pn = reinterpret_cast<const float4*>(W_hh + ((size_t)(2 * HDIM + i) * HDIM + sh * KH));
        #pragma unroll
        for (int q = 0; q < 6; q++) {
            float4 v;
            v = pr[q]; whr[2*q] = make_float2(v.x, v.y); whr[2*q+1] = make_float2(v.z, v.w);
            v = pz[q]; whz[2*q] = make_float2(v.x, v.y); whz[2*q+1] = make_float2(v.z, v.w);
            v = pn[q]; whn[2*q] = make_float2(v.x, v.y); whn[2*q+1] = make_float2(v.z, v.w);
        }
    }
    // ---- gi weights: d-half (3 inputs), partial folded into the shuffles ----
    float wir[3], wiz[3], win[3];
    #pragma unroll
    for (int j = 0; j < 3; j++) {
        wir[j] = W_ih[(size_t)(0 * HDIM + i) * D_IN + sh * 3 + j];
        wiz[j] = W_ih[(size_t)(1 * HDIM + i) * D_IN + sh * 3 + j];
        win[j] = W_ih[(size_t)(2 * HDIM + i) * D_IN + sh * 3 + j];
    }
    const float brr = b_ih[i]            + b_hh[i];
    const float bzz = b_ih[HDIM + i]     + b_hh[HDIM + i];
    const float bin = b_ih[2 * HDIM + i];
    const float bhn = b_hh[2 * HDIM + i];

    // ---- fc role ----
    const int i2   = tid % HDIM;
    const int rcA  = tid / HDIM;         // 0 or 1 (also handles rcA+2)
    const int d_fc = i2 >> 3;
    const int c_fc = i2 & 7;             // == lane&7 for all tid (48%8==0)
    float2 fw[3];
    {
        const float2* p = reinterpret_cast<const float2*>(fc_w + (size_t)d_fc * HDIM + c_fc * 6);
        fw[0] = p[0]; fw[1] = p[1]; fw[2] = p[2];
    }
    const float fb = fc_b[d_fc];
    float* yA = y + (size_t)(b0 + rcA)     * T_SEQ * D_IN;
    float* yB = y + (size_t)(b0 + rcA + 2) * T_SEQ * D_IN;
    const bool vA = (b0 + rcA)     < B;
    const bool vB = (b0 + rcA + 2) < B;

    // ---- init ----
    float hc[2] = {0.0f, 0.0f};          // states for rows 2*sh, 2*sh+1 (output i)
    #pragma unroll
    for (int r = 0; r < R; r++) { if (sh == 0) h_s[0][r][i] = 0.0f; }
    if (tid < R * D_IN) {
        int rr = tid / D_IN, dd = tid - rr * D_IN;
        x_s[0][rr][dd] = ((b0 + rr) < B) ? x[((size_t)(b0 + rr) * T_SEQ) * D_IN + dd] : 0.0f;
    }
    __syncthreads();

    const float2 z2 = make_float2(0.0f, 0.0f);
    int p = 0;

    for (int t = 0; t < T_SEQ; t++) {
        // ---- prefetch x[t+1] ----
        float xn = 0.0f;
        if (tid < R * D_IN && (t + 1) < T_SEQ) {
            int rr = tid / D_IN, dd = tid - rr * D_IN;
            if ((b0 + rr) < B) xn = x[((size_t)(b0 + rr) * T_SEQ + (t + 1)) * D_IN + dd];
        }

        // ---- P1: half-dots + shfl exchange, all 4 rows ----
        float fr[2], fz[2], fhn[2], fgn[2];
        #pragma unroll
        for (int r = 0; r < R; r++) {
            float2 a_r = z2, a_z = z2, a_n = z2;
            const float4* h4 = reinterpret_cast<const float4*>(&h_s[p][r][sh * KH]);
            #pragma unroll
            for (int q = 0; q < 6; q++) {
                float4 hv = h4[q];
                float2 h01 = make_float2(hv.x, hv.y);
                float2 h23 = make_float2(hv.z, hv.w);
                a_r = ffma2(whr[2*q], h01, a_r); a_r = ffma2(whr[2*q+1], h23, a_r);
                a_z = ffma2(whz[2*q], h01, a_z); a_z = ffma2(whz[2*q+1], h23, a_z);
                a_n = ffma2(whn[2*q], h01, a_n); a_n = ffma2(whn[2*q+1], h23, a_n);
            }
            float g_r = 0.f, g_z = 0.f, g_n = 0.f;
            #pragma unroll
            for (int j = 0; j < 3; j++) {
                float xv = x_s[p][r][sh * 3 + j];
                g_r = fmaf(wir[j], xv, g_r);
                g_z = fmaf(wiz[j], xv, g_z);
                g_n = fmaf(win[j], xv, g_n);
            }
            float sr  = a_r.x + a_r.y + g_r;     // gh_r half + gi_r half
            float sz  = a_z.x + a_z.y + g_z;
            float shn = a_n.x + a_n.y;            // gh_n half (separate)
            float sgn = g_n;                      // gi_n half (separate)
            sr  += __shfl_xor_sync(0xffffffffu, sr,  16);
            sz  += __shfl_xor_sync(0xffffffffu, sz,  16);
            shn += __shfl_xor_sync(0xffffffffu, shn, 16);
            sgn += __shfl_xor_sync(0xffffffffu, sgn, 16);
            if (sh == (r >> 1)) {                 // stash: my row-pair only
                fr[r & 1] = sr; fz[r & 1] = sz; fhn[r & 1] = shn; fgn[r & 1] = sgn;
            }
        }

        // ---- fused fc on h_{t-1} (h_s[p] untouched this step) ----
        if (t > 0) {
            const float2* hcA = reinterpret_cast<const float2*>(&h_s[p][rcA][c_fc * 6]);
            const float2* hcB = reinterpret_cast<const float2*>(&h_s[p][rcA + 2][c_fc * 6]);
            float2 aA = ffma2(fw[0], hcA[0], z2);
            float2 aB = ffma2(fw[0], hcB[0], z2);
            aA = ffma2(fw[1], hcA[1], aA);
            aB = ffma2(fw[1], hcB[1], aB);
            aA = ffma2(fw[2], hcA[2], aA);
            aB = ffma2(fw[2], hcB[2], aB);
            float pA = aA.x + aA.y;
            float pB = aB.x + aB.y;
            pA += __shfl_down_sync(0xffffffffu, pA, 4, 8);
            pB += __shfl_down_sync(0xffffffffu, pB, 4, 8);
            pA += __shfl_down_sync(0xffffffffu, pA, 2, 8);
            pB += __shfl_down_sync(0xffffffffu, pB, 2, 8);
            pA += __shfl_down_sync(0xffffffffu, pA, 1, 8);
            pB += __shfl_down_sync(0xffffffffu, pB, 1, 8);
            if (c_fc == 0) {
                if (vA) yA[(size_t)(t - 1) * D_IN + d_fc] = pA + fb;
                if (vB) yB[(size_t)(t - 1) * D_IN + d_fc] = pB + fb;
            }
        }

        // ---- combine: lanes sh finish rows 2*sh, 2*sh+1 (non-redundant MUFU) ----
        #pragma unroll
        for (int c = 0; c < 2; c++) {
            float rg = fast_sigmoid(fr[c] + brr);
            float zg = fast_sigmoid(fz[c] + bzz);
            float ng = fast_tanh((fgn[c] + bin) + rg * (fhn[c] + bhn));
            hc[c] = ng + zg * (hc[c] - ng);
            h_s[p ^ 1][2 * sh + c][i] = hc[c];
        }
        if (tid < R * D_IN) {
            int rr = tid / D_IN, dd = tid - rr * D_IN;
            x_s[p ^ 1][rr][dd] = xn;
        }
        __syncthreads();
        p ^= 1;
    }

    // ---- fc for final h_{T-1} ----
    {
        const float2* hcA = reinterpret_cast<const float2*>(&h_s[p][rcA][c_fc * 6]);
        const float2* hcB = reinterpret_cast<const float2*>(&h_s[p][rcA + 2][c_fc * 6]);
        float2 aA = ffma2(fw[0], hcA[0], z2);
        float2 aB = ffma2(fw[0], hcB[0], z2);
        aA = ffma2(fw[1], hcA[1], aA);
        aB = ffma2(fw[1], hcB[1], aB);
        aA = ffma2(fw[2], hcA[2], aA);
        aB = ffma2(fw[2], hcB[2], aB);
        float pA = aA.x + aA.y;
        float pB = aB.x + aB.y;
        pA += __shfl_down_sync(0xffffffffu, pA, 4, 8);
        pB += __shfl_down_sync(0xffffffffu, pB, 4, 8);
        pA += __shfl_down_sync(0xffffffffu, pA, 2, 8);
        pB += __shfl_down_sync(0xffffffffu, pB, 2, 8);
        pA += __shfl_down_sync(0xffffffffu, pA, 1, 8);
        pB += __shfl_down_sync(0xffffffffu, pB, 1, 8);
        if (c_fc == 0) {
            if (vA) yA[(size_t)(T_SEQ - 1) * D_IN + d_fc] = pA + fb;
            if (vB) yB[(size_t)(T_SEQ - 1) * D_IN + d_fc] = pB + fb;
        }
    }
}

extern "C" void kernel_launch(void* const* d_in, const int* in_sizes, int n_in,
                              void* d_out, int out_size)
{
    const float* x    = (const float*)d_in[0];
    const float* W_ih = (const float*)d_in[1];
    const float* W_hh = (const float*)d_in[2];
    const float* b_ih = (const float*)d_in[3];
    const float* b_hh = (const float*)d_in[4];
    const float* fc_w = (const float*)d_in[5];
    const float* fc_b = (const float*)d_in[6];
    float* y = (float*)d_out;

    int B = in_sizes[0] / (T_SEQ * D_IN);
    int blocks = (B + R - 1) / R;
    gru_fused_kernel<<<blocks, NTHR>>>(x, W_ih, W_hh, b_ih, b_hh, fc_w, fc_b, y, B);
}